// round 14
// baseline (speedup 1.0000x reference)
#include <cuda_runtime.h>

#define CM 256
#define CZ 128
#define NRES 768
#define SDIM 128
#define LN_EPS 1e-5f

// Block-role layout (single fused kernel, 256 threads/block). Copy blocks are
// LAST so the final partial waves are pure high-MLP copy (saturates DRAM in
// the tail); z blocks start in wave 1 and their latency-hidden table guard
// absorbs the brief overlap with the 16 setup blocks (also wave-1 resident):
//   [0, 16)              : table setup (one bin per block)
//   [16, 16+96)          : m row-0 LN-add, 8 rows/block
//   [112, 112+36864)     : z path, 16 rows/block (2 rows/warp)
//   [36976, 36976+6096)  : bulk m copy (skipping slice 0), 4 float4/thread
#define NSETUP       16
#define NM_BLOCKS    96      // 768 / 8
#define NZ_BLOCKS    36864   // 589824 / 16
#define NCOPY_BLOCKS 6096    // (25165824 - 196608)/4/1024
#define M_BASE       NSETUP
#define Z_BASE       (NSETUP + NM_BLOCKS)
#define COPY_BASE    (NSETUP + NM_BLOCKS + NZ_BLOCKS)
#define GRID_TOTAL   (NSETUP + NM_BLOCKS + NZ_BLOCKS + NCOPY_BLOCKS)
#define M_ELEMS      25165824
#define M_SKIP4      49152   // 768*256/4

// tab_g[k][c] = lin_w[c*15+k] + lin_b[c] + ln_z_b[c] (k<15); tab_g[15][c] = lin_b[c]+ln_z_b[c]
__device__ float tab_g[16 * CZ];
// Monotonic completion counter: +16 per launch; consumers need >= 16.
// Replays see >=16 immediately and the table contents are identical -> deterministic.
__device__ unsigned int tab_flag = 0;

__global__ void __launch_bounds__(256, 8) fused_kernel(
        const float* __restrict__ m,
        const float* __restrict__ z,
        const float* __restrict__ m_prev,
        const float* __restrict__ z_prev,
        const float* __restrict__ x,
        const float* __restrict__ ln_m_w,
        const float* __restrict__ ln_m_b,
        const float* __restrict__ ln_z_w,
        const float* __restrict__ ln_z_b,
        const float* __restrict__ lin_w,
        const float* __restrict__ lin_b,
        float* __restrict__ out) {

    float* out_z = out + M_ELEMS;
    const unsigned bid = blockIdx.x;

    if (bid >= Z_BASE && bid < COPY_BASE) {
        // ------------------------------------------------------------------
        // z path: out_z[row,:] = z[row,:] + LN(z_prev[row,:]) + tab[bin,:]
        // 2 rows per warp: half-warp per row, 8 floats per lane.
        //
        // Table guard, latency-hidden: tid0 issues a fire-and-forget L2 read
        // of the flag NOW; it is consumed only after the whole load+reduce
        // phase (~700+ cyc), which covers the L2 round trip. Wave-1 z blocks
        // may spin briefly until the 16 setup blocks (<1us) release; all
        // later blocks sail through.
        // ------------------------------------------------------------------
        unsigned f = 16u;
        if (threadIdx.x == 0)
            asm volatile("ld.global.cg.u32 %0, [%1];" : "=r"(f) : "l"(&tab_flag));

        int zb   = bid - Z_BASE;
        int wid  = threadIdx.x >> 5;
        int lane = threadIdx.x & 31;
        int h    = lane & 15;
        int row  = zb * 16 + wid * 2 + (lane >> 4);

        int i = row / NRES;
        int j = row - i * NRES;

        // Distance with UNFUSED fp32 arithmetic — matches the reference's
        // (dx*dx + dy*dy) + dz*dz rounding so edge-adjacent d values bin
        // identically.
        float dx = x[3 * i + 0] - x[3 * j + 0];
        float dy = x[3 * i + 1] - x[3 * j + 1];
        float dz = x[3 * i + 2] - x[3 * j + 2];
        float s2 = __fadd_rn(__fadd_rn(__fmul_rn(dx, dx), __fmul_rn(dy, dy)),
                             __fmul_rn(dz, dz));
        float d  = sqrtf(s2);

        // Robust bin: clamp k0 to 15 so d >> 20.75 still tests the open-ended
        // bin 14 (candidates {14,15,16}); +/-1 loop absorbs floor() rounding;
        // edges 3.25+1.25k are fp32-exact so the test matches the reference.
        int bin = 15;
        int k0 = (int)floorf((d - 3.25f) * 0.8f);
        if (k0 > 15) k0 = 15;
        #pragma unroll
        for (int dk = -1; dk <= 1; dk++) {
            int k = k0 + dk;
            if (k >= 0 && k <= 14) {
                float lo = fmaf(1.25f, (float)k, 3.25f);
                float hi = (k == 14) ? 1e8f : (lo + 1.25f);
                if (d > lo && d < hi) bin = k;
            }
        }

        const float4* zp = reinterpret_cast<const float4*>(z_prev + (size_t)row * CZ);
        float4 v0 = __ldcs(zp + h);
        float4 v1 = __ldcs(zp + h + 16);

        // Independent streaming loads issued before the guard barrier.
        const float4* zr = reinterpret_cast<const float4*>(z + (size_t)row * CZ);
        const float4* wv = reinterpret_cast<const float4*>(ln_z_w);
        float4 a0 = __ldcs(zr + h);
        float4 a1 = __ldcs(zr + h + 16);
        float4 w0 = wv[h];
        float4 w1 = wv[h + 16];

        float s  = v0.x + v0.y + v0.z + v0.w + v1.x + v1.y + v1.z + v1.w;
        float ss = v0.x*v0.x + v0.y*v0.y + v0.z*v0.z + v0.w*v0.w
                 + v1.x*v1.x + v1.y*v1.y + v1.z*v1.z + v1.w*v1.w;
        #pragma unroll
        for (int o = 8; o; o >>= 1) {
            s  += __shfl_xor_sync(0xffffffffu, s,  o);
            ss += __shfl_xor_sync(0xffffffffu, ss, o);
        }
        float mu   = s * (1.0f / CZ);
        float var  = ss * (1.0f / CZ) - mu * mu;
        float rstd = rsqrtf(var + LN_EPS);

        // Consume the guard: by now the early flag read has landed. Spin only
        // while setup blocks are still running; acquire orders the tab reads.
        if (threadIdx.x == 0 && f < 16u) {
            unsigned g;
            do {
                asm volatile("ld.acquire.gpu.u32 %0, [%1];" : "=r"(g) : "l"(&tab_flag) : "memory");
                if (g >= 16u) break;
                __nanosleep(64);
            } while (true);
        }
        __syncthreads();

        const float4* tv = reinterpret_cast<const float4*>(&tab_g[bin * CZ]);
        float4* ov = reinterpret_cast<float4*>(out_z + (size_t)row * CZ);

        {
            float4 t = tv[h];
            float4 o;
            o.x = a0.x + t.x + (v0.x - mu) * rstd * w0.x;
            o.y = a0.y + t.y + (v0.y - mu) * rstd * w0.y;
            o.z = a0.z + t.z + (v0.z - mu) * rstd * w0.z;
            o.w = a0.w + t.w + (v0.w - mu) * rstd * w0.w;
            __stcs(ov + h, o);
        }
        {
            float4 t = tv[h + 16];
            float4 o;
            o.x = a1.x + t.x + (v1.x - mu) * rstd * w1.x;
            o.y = a1.y + t.y + (v1.y - mu) * rstd * w1.y;
            o.z = a1.z + t.z + (v1.z - mu) * rstd * w1.z;
            o.w = a1.w + t.w + (v1.w - mu) * rstd * w1.w;
            __stcs(ov + h + 16, o);
        }
    } else if (bid < NSETUP) {
        // ------------------------------------------------------------------
        // Table setup: block k computes tab_g[k][0..127]; release via flag.
        // bid 0-15 are wave-1 resident, so consumer waits are bounded.
        // ------------------------------------------------------------------
        int k = bid;
        int c = threadIdx.x;
        if (c < CZ) {
            float v = lin_b[c] + ln_z_b[c];
            if (k < 15) v += lin_w[c * 15 + k];
            tab_g[k * CZ + c] = v;
        }
        __syncthreads();
        if (threadIdx.x == 0) {
            __threadfence();                       // release tab_g writes
            atomicAdd(&tab_flag, 1u);
        }
    } else if (bid < Z_BASE) {
        // ------------------------------------------------------------------
        // m slice 0: out[0,n,:] = m[0,n,:] + LN(m_prev[0,n,:])
        // 1 warp per row, 8 rows/block.
        // ------------------------------------------------------------------
        int mb   = bid - M_BASE;
        int wid  = threadIdx.x >> 5;
        int lane = threadIdx.x & 31;
        int row  = mb * 8 + wid;

        const float4* mp = reinterpret_cast<const float4*>(m_prev + (size_t)row * CM);
        float4 a = mp[lane];
        float4 b = mp[lane + 32];

        float s  = a.x + a.y + a.z + a.w + b.x + b.y + b.z + b.w;
        float ss = a.x*a.x + a.y*a.y + a.z*a.z + a.w*a.w
                 + b.x*b.x + b.y*b.y + b.z*b.z + b.w*b.w;
        #pragma unroll
        for (int o = 16; o; o >>= 1) {
            s  += __shfl_xor_sync(0xffffffffu, s,  o);
            ss += __shfl_xor_sync(0xffffffffu, ss, o);
        }
        float mu   = s * (1.0f / CM);
        float var  = ss * (1.0f / CM) - mu * mu;
        float rstd = rsqrtf(var + LN_EPS);

        const float4* mr = reinterpret_cast<const float4*>(m + (size_t)row * CM);
        const float4* wv = reinterpret_cast<const float4*>(ln_m_w);
        const float4* bv = reinterpret_cast<const float4*>(ln_m_b);
        float4* ov = reinterpret_cast<float4*>(out + (size_t)row * CM);

        {
            float4 mm = mr[lane], w = wv[lane], bb = bv[lane];
            float4 o;
            o.x = mm.x + (a.x - mu) * rstd * w.x + bb.x;
            o.y = mm.y + (a.y - mu) * rstd * w.y + bb.y;
            o.z = mm.z + (a.z - mu) * rstd * w.z + bb.z;
            o.w = mm.w + (a.w - mu) * rstd * w.w + bb.w;
            ov[lane] = o;
        }
        {
            float4 mm = mr[lane + 32], w = wv[lane + 32], bb = bv[lane + 32];
            float4 o;
            o.x = mm.x + (b.x - mu) * rstd * w.x + bb.x;
            o.y = mm.y + (b.y - mu) * rstd * w.y + bb.y;
            o.z = mm.z + (b.z - mu) * rstd * w.z + bb.z;
            o.w = mm.w + (b.w - mu) * rstd * w.w + bb.w;
            ov[lane + 32] = o;
        }
    } else {
        // ------------------------------------------------------------------
        // bulk copy of m[1:,...] -> out : 4 float4/thread (lean: 32 regs).
        // Placed LAST so the final partial waves are pure copy — 4 independent
        // float4 loads/thread keep DRAM saturated through the grid tail.
        // ------------------------------------------------------------------
        unsigned cb = bid - COPY_BASE;
        const float4* src = reinterpret_cast<const float4*>(m);
        float4* dst = reinterpret_cast<float4*>(out);
        size_t base = (size_t)M_SKIP4 + (size_t)cb * 1024 + threadIdx.x;
        #pragma unroll
        for (int k = 0; k < 4; k++)
            __stcs(dst + base + k * 256, __ldcs(src + base + k * 256));
    }
}

extern "C" void kernel_launch(void* const* d_in, const int* in_sizes, int n_in,
                              void* d_out, int out_size) {
    const float* m      = (const float*)d_in[0];
    const float* z      = (const float*)d_in[1];
    const float* m_prev = (const float*)d_in[2];
    const float* z_prev = (const float*)d_in[3];
    const float* x_prev = (const float*)d_in[4];
    const float* ln_m_w = (const float*)d_in[5];
    const float* ln_m_b = (const float*)d_in[6];
    const float* ln_z_w = (const float*)d_in[7];
    const float* ln_z_b = (const float*)d_in[8];
    const float* lin_w  = (const float*)d_in[9];
    const float* lin_b  = (const float*)d_in[10];

    fused_kernel<<<GRID_TOTAL, 256>>>(
        m, z, m_prev, z_prev, x_prev,
        ln_m_w, ln_m_b, ln_z_w, ln_z_b, lin_w, lin_b, (float*)d_out);
}

// round 15
// speedup vs baseline: 1.0090x; 1.0090x over previous
#include <cuda_runtime.h>

#define CM 256
#define CZ 128
#define NRES 768
#define SDIM 128
#define LN_EPS 1e-5f

// Block-role layout (single fused kernel, 256 threads/block), ordered so that
// wave 1 = setup + copy blocks (setup overlaps copy; z blocks start waves later,
// so their table guard never actually spins):
//   [0, 16)            : table setup (one bin per block)
//   [16, 16+6096)      : bulk m copy (skipping slice 0), 4 float4/thread
//   [6112, 6112+96)    : m row-0 LN-add, 8 rows/block
//   [6208, 6208+36864) : z path, 16 rows/block (2 rows/warp)
#define NSETUP       16
#define NCOPY_BLOCKS 6096    // (25165824 - 196608)/4/1024
#define NM_BLOCKS    96      // 768 / 8
#define NZ_BLOCKS    36864   // 589824 / 16
#define COPY_BASE    NSETUP
#define M_BASE       (NSETUP + NCOPY_BLOCKS)
#define Z_BASE       (NSETUP + NCOPY_BLOCKS + NM_BLOCKS)
#define GRID_TOTAL   (NSETUP + NCOPY_BLOCKS + NM_BLOCKS + NZ_BLOCKS)
#define M_ELEMS      25165824
#define M_SKIP4      49152   // 768*256/4

// tab_g[k][c] = lin_w[c*15+k] + lin_b[c] + ln_z_b[c] (k<15); tab_g[15][c] = lin_b[c]+ln_z_b[c]
__device__ float tab_g[16 * CZ];
// Monotonic completion counter: +16 per launch; consumers need >= 16.
// Replays see >=16 immediately and the table contents are identical -> deterministic.
__device__ unsigned int tab_flag = 0;

__global__ void __launch_bounds__(256, 8) fused_kernel(
        const float* __restrict__ m,
        const float* __restrict__ z,
        const float* __restrict__ m_prev,
        const float* __restrict__ z_prev,
        const float* __restrict__ x,
        const float* __restrict__ ln_m_w,
        const float* __restrict__ ln_m_b,
        const float* __restrict__ ln_z_w,
        const float* __restrict__ ln_z_b,
        const float* __restrict__ lin_w,
        const float* __restrict__ lin_b,
        float* __restrict__ out) {

    float* out_z = out + M_ELEMS;
    const unsigned bid = blockIdx.x;

    if (bid >= Z_BASE) {
        // ------------------------------------------------------------------
        // z path: out_z[row,:] = z[row,:] + LN(z_prev[row,:]) + tab[bin,:]
        // 2 rows per warp: half-warp per row, 8 floats per lane.
        //
        // Table guard, latency-hidden: tid0 issues a fire-and-forget L2 read
        // of the flag NOW; it is consumed only after the whole load+reduce
        // phase (~700+ cyc), which covers the L2 round trip. Steady state:
        // no spin, no exposed latency.
        // ------------------------------------------------------------------
        unsigned f = 16u;
        if (threadIdx.x == 0)
            asm volatile("ld.global.cg.u32 %0, [%1];" : "=r"(f) : "l"(&tab_flag));

        int zb   = bid - Z_BASE;
        int wid  = threadIdx.x >> 5;
        int lane = threadIdx.x & 31;
        int h    = lane & 15;
        int row  = zb * 16 + wid * 2 + (lane >> 4);

        int i = row / NRES;
        int j = row - i * NRES;

        // Distance with UNFUSED fp32 arithmetic — matches the reference's
        // (dx*dx + dy*dy) + dz*dz rounding so edge-adjacent d values bin
        // identically.
        float dx = x[3 * i + 0] - x[3 * j + 0];
        float dy = x[3 * i + 1] - x[3 * j + 1];
        float dz = x[3 * i + 2] - x[3 * j + 2];
        float s2 = __fadd_rn(__fadd_rn(__fmul_rn(dx, dx), __fmul_rn(dy, dy)),
                             __fmul_rn(dz, dz));
        float d  = sqrtf(s2);

        // Robust bin: clamp k0 to 15 so d >> 20.75 still tests the open-ended
        // bin 14 (candidates {14,15,16}); +/-1 loop absorbs floor() rounding;
        // edges 3.25+1.25k are fp32-exact so the test matches the reference.
        int bin = 15;
        int k0 = (int)floorf((d - 3.25f) * 0.8f);
        if (k0 > 15) k0 = 15;
        #pragma unroll
        for (int dk = -1; dk <= 1; dk++) {
            int k = k0 + dk;
            if (k >= 0 && k <= 14) {
                float lo = fmaf(1.25f, (float)k, 3.25f);
                float hi = (k == 14) ? 1e8f : (lo + 1.25f);
                if (d > lo && d < hi) bin = k;
            }
        }

        const float4* zp = reinterpret_cast<const float4*>(z_prev + (size_t)row * CZ);
        float4 v0 = __ldcs(zp + h);
        float4 v1 = __ldcs(zp + h + 16);

        // Independent streaming loads issued before the guard barrier.
        const float4* zr = reinterpret_cast<const float4*>(z + (size_t)row * CZ);
        const float4* wv = reinterpret_cast<const float4*>(ln_z_w);
        float4 a0 = __ldcs(zr + h);
        float4 a1 = __ldcs(zr + h + 16);
        float4 w0 = wv[h];
        float4 w1 = wv[h + 16];

        float s  = v0.x + v0.y + v0.z + v0.w + v1.x + v1.y + v1.z + v1.w;
        float ss = v0.x*v0.x + v0.y*v0.y + v0.z*v0.z + v0.w*v0.w
                 + v1.x*v1.x + v1.y*v1.y + v1.z*v1.z + v1.w*v1.w;
        #pragma unroll
        for (int o = 8; o; o >>= 1) {
            s  += __shfl_xor_sync(0xffffffffu, s,  o);
            ss += __shfl_xor_sync(0xffffffffu, ss, o);
        }
        float mu   = s * (1.0f / CZ);
        float var  = ss * (1.0f / CZ) - mu * mu;
        float rstd = rsqrtf(var + LN_EPS);

        // Consume the guard: by now the early flag read has landed. Spin only
        // on the (rare) first-wave race; acquire orders the tab reads below.
        if (threadIdx.x == 0 && f < 16u) {
            unsigned g;
            do {
                asm volatile("ld.acquire.gpu.u32 %0, [%1];" : "=r"(g) : "l"(&tab_flag) : "memory");
                if (g >= 16u) break;
                __nanosleep(64);
            } while (true);
        }
        __syncthreads();

        const float4* tv = reinterpret_cast<const float4*>(&tab_g[bin * CZ]);
        float4* ov = reinterpret_cast<float4*>(out_z + (size_t)row * CZ);

        {
            float4 t = tv[h];
            float4 o;
            o.x = a0.x + t.x + (v0.x - mu) * rstd * w0.x;
            o.y = a0.y + t.y + (v0.y - mu) * rstd * w0.y;
            o.z = a0.z + t.z + (v0.z - mu) * rstd * w0.z;
            o.w = a0.w + t.w + (v0.w - mu) * rstd * w0.w;
            __stcs(ov + h, o);
        }
        {
            float4 t = tv[h + 16];
            float4 o;
            o.x = a1.x + t.x + (v1.x - mu) * rstd * w1.x;
            o.y = a1.y + t.y + (v1.y - mu) * rstd * w1.y;
            o.z = a1.z + t.z + (v1.z - mu) * rstd * w1.z;
            o.w = a1.w + t.w + (v1.w - mu) * rstd * w1.w;
            __stcs(ov + h + 16, o);
        }
    } else if (bid < NSETUP) {
        // ------------------------------------------------------------------
        // Table setup: block k computes tab_g[k][0..127]; release via flag.
        // bid 0-15 are wave-1 resident, so consumer waits are bounded.
        // ------------------------------------------------------------------
        int k = bid;
        int c = threadIdx.x;
        if (c < CZ) {
            float v = lin_b[c] + ln_z_b[c];
            if (k < 15) v += lin_w[c * 15 + k];
            tab_g[k * CZ + c] = v;
        }
        __syncthreads();
        if (threadIdx.x == 0) {
            __threadfence();                       // release tab_g writes
            atomicAdd(&tab_flag, 1u);
        }
    } else if (bid < M_BASE) {
        // ------------------------------------------------------------------
        // bulk copy of m[1:,...] -> out : 4 float4/thread (lean: 32 regs)
        // ------------------------------------------------------------------
        unsigned cb = bid - COPY_BASE;
        const float4* src = reinterpret_cast<const float4*>(m);
        float4* dst = reinterpret_cast<float4*>(out);
        size_t base = (size_t)M_SKIP4 + (size_t)cb * 1024 + threadIdx.x;
        #pragma unroll
        for (int k = 0; k < 4; k++)
            __stcs(dst + base + k * 256, __ldcs(src + base + k * 256));
    } else {
        // ------------------------------------------------------------------
        // m slice 0: out[0,n,:] = m[0,n,:] + LN(m_prev[0,n,:])
        // 1 warp per row, 8 rows/block.
        // ------------------------------------------------------------------
        int mb   = bid - M_BASE;
        int wid  = threadIdx.x >> 5;
        int lane = threadIdx.x & 31;
        int row  = mb * 8 + wid;

        const float4* mp = reinterpret_cast<const float4*>(m_prev + (size_t)row * CM);
        float4 a = mp[lane];
        float4 b = mp[lane + 32];

        float s  = a.x + a.y + a.z + a.w + b.x + b.y + b.z + b.w;
        float ss = a.x*a.x + a.y*a.y + a.z*a.z + a.w*a.w
                 + b.x*b.x + b.y*b.y + b.z*b.z + b.w*b.w;
        #pragma unroll
        for (int o = 16; o; o >>= 1) {
            s  += __shfl_xor_sync(0xffffffffu, s,  o);
            ss += __shfl_xor_sync(0xffffffffu, ss, o);
        }
        float mu   = s * (1.0f / CM);
        float var  = ss * (1.0f / CM) - mu * mu;
        float rstd = rsqrtf(var + LN_EPS);

        const float4* mr = reinterpret_cast<const float4*>(m + (size_t)row * CM);
        const float4* wv = reinterpret_cast<const float4*>(ln_m_w);
        const float4* bv = reinterpret_cast<const float4*>(ln_m_b);
        float4* ov = reinterpret_cast<float4*>(out + (size_t)row * CM);

        {
            float4 mm = mr[lane], w = wv[lane], bb = bv[lane];
            float4 o;
            o.x = mm.x + (a.x - mu) * rstd * w.x + bb.x;
            o.y = mm.y + (a.y - mu) * rstd * w.y + bb.y;
            o.z = mm.z + (a.z - mu) * rstd * w.z + bb.z;
            o.w = mm.w + (a.w - mu) * rstd * w.w + bb.w;
            ov[lane] = o;
        }
        {
            float4 mm = mr[lane + 32], w = wv[lane + 32], bb = bv[lane + 32];
            float4 o;
            o.x = mm.x + (b.x - mu) * rstd * w.x + bb.x;
            o.y = mm.y + (b.y - mu) * rstd * w.y + bb.y;
            o.z = mm.z + (b.z - mu) * rstd * w.z + bb.z;
            o.w = mm.w + (b.w - mu) * rstd * w.w + bb.w;
            ov[lane + 32] = o;
        }
    }
}

extern "C" void kernel_launch(void* const* d_in, const int* in_sizes, int n_in,
                              void* d_out, int out_size) {
    const float* m      = (const float*)d_in[0];
    const float* z      = (const float*)d_in[1];
    const float* m_prev = (const float*)d_in[2];
    const float* z_prev = (const float*)d_in[3];
    const float* x_prev = (const float*)d_in[4];
    const float* ln_m_w = (const float*)d_in[5];
    const float* ln_m_b = (const float*)d_in[6];
    const float* ln_z_w = (const float*)d_in[7];
    const float* ln_z_b = (const float*)d_in[8];
    const float* lin_w  = (const float*)d_in[9];
    const float* lin_b  = (const float*)d_in[10];

    fused_kernel<<<GRID_TOTAL, 256>>>(
        m, z, m_prev, z_prev, x_prev,
        ln_m_w, ln_m_b, ln_z_w, ln_z_b, lin_w, lin_b, (float*)d_out);
}

// round 16
// speedup vs baseline: 1.0124x; 1.0034x over previous
#include <cuda_runtime.h>

#define CM 256
#define CZ 128
#define NRES 768
#define SDIM 128
#define LN_EPS 1e-5f

// Block-role layout (single fused kernel, 256 threads/block):
//   [0, 16)            : table setup (one bin per block)
//   [16, 16+6096)      : bulk m copy (skipping slice 0), 4 float4/thread
//   [6112, 6112+96)    : m row-0 LN-add, 8 rows/block
//   [6208, 6208+36864) : z path, 16 rows/block (2 rows/warp)
//
// Ordering argument (why the z path needs NO table guard): blocks are
// dispatched in bid order; a z block (bid >= 6208) can only be dispatched
// after 6208-1184 = 5024 earlier blocks have RETIRED (1184 = 148 SMs x 8
// resident blocks). The 6096 copy blocks between setup and z each move 16KB
// (>= 1us lifetime), i.e. >= 4 full block generations of wall time separate
// setup retirement from the first z dispatch. Setup blocks (bid 0-15, wave-1
// resident, ~300ns) end with __threadfence, so their tab_g stores are
// L2-visible long before any z block issues its first load. tab_g is never
// read before the z phase, so no SM can hold a stale L1 copy. This holds
// identically on every replay (deterministic dispatch).
#define NSETUP       16
#define NCOPY_BLOCKS 6096    // (25165824 - 196608)/4/1024
#define NM_BLOCKS    96      // 768 / 8
#define NZ_BLOCKS    36864   // 589824 / 16
#define COPY_BASE    NSETUP
#define M_BASE       (NSETUP + NCOPY_BLOCKS)
#define Z_BASE       (NSETUP + NCOPY_BLOCKS + NM_BLOCKS)
#define GRID_TOTAL   (NSETUP + NCOPY_BLOCKS + NM_BLOCKS + NZ_BLOCKS)
#define M_ELEMS      25165824
#define M_SKIP4      49152   // 768*256/4

// tab_g[k][c] = lin_w[c*15+k] + lin_b[c] + ln_z_b[c] (k<15); tab_g[15][c] = lin_b[c]+ln_z_b[c]
__device__ float tab_g[16 * CZ];

__global__ void __launch_bounds__(256, 8) fused_kernel(
        const float* __restrict__ m,
        const float* __restrict__ z,
        const float* __restrict__ m_prev,
        const float* __restrict__ z_prev,
        const float* __restrict__ x,
        const float* __restrict__ ln_m_w,
        const float* __restrict__ ln_m_b,
        const float* __restrict__ ln_z_w,
        const float* __restrict__ ln_z_b,
        const float* __restrict__ lin_w,
        const float* __restrict__ lin_b,
        float* __restrict__ out) {

    float* out_z = out + M_ELEMS;
    const unsigned bid = blockIdx.x;

    if (bid >= Z_BASE) {
        // ------------------------------------------------------------------
        // z path: out_z[row,:] = z[row,:] + LN(z_prev[row,:]) + tab[bin,:]
        // 2 rows per warp: half-warp per row, 8 floats per lane.
        // No guard needed — see ordering argument above.
        // ------------------------------------------------------------------
        int zb   = bid - Z_BASE;
        int wid  = threadIdx.x >> 5;
        int lane = threadIdx.x & 31;
        int h    = lane & 15;
        int row  = zb * 16 + wid * 2 + (lane >> 4);

        int i = row / NRES;
        int j = row - i * NRES;

        // Distance with UNFUSED fp32 arithmetic — matches the reference's
        // (dx*dx + dy*dy) + dz*dz rounding so edge-adjacent d values bin
        // identically.
        float dx = x[3 * i + 0] - x[3 * j + 0];
        float dy = x[3 * i + 1] - x[3 * j + 1];
        float dz = x[3 * i + 2] - x[3 * j + 2];
        float s2 = __fadd_rn(__fadd_rn(__fmul_rn(dx, dx), __fmul_rn(dy, dy)),
                             __fmul_rn(dz, dz));
        float d  = sqrtf(s2);

        // Robust bin: clamp k0 to 15 so d >> 20.75 still tests the open-ended
        // bin 14 (candidates {14,15,16}); +/-1 loop absorbs floor() rounding;
        // edges 3.25+1.25k are fp32-exact so the test matches the reference.
        int bin = 15;
        int k0 = (int)floorf((d - 3.25f) * 0.8f);
        if (k0 > 15) k0 = 15;
        #pragma unroll
        for (int dk = -1; dk <= 1; dk++) {
            int k = k0 + dk;
            if (k >= 0 && k <= 14) {
                float lo = fmaf(1.25f, (float)k, 3.25f);
                float hi = (k == 14) ? 1e8f : (lo + 1.25f);
                if (d > lo && d < hi) bin = k;
            }
        }

        const float4* zp = reinterpret_cast<const float4*>(z_prev + (size_t)row * CZ);
        float4 v0 = __ldcs(zp + h);
        float4 v1 = __ldcs(zp + h + 16);

        float s  = v0.x + v0.y + v0.z + v0.w + v1.x + v1.y + v1.z + v1.w;
        float ss = v0.x*v0.x + v0.y*v0.y + v0.z*v0.z + v0.w*v0.w
                 + v1.x*v1.x + v1.y*v1.y + v1.z*v1.z + v1.w*v1.w;
        #pragma unroll
        for (int o = 8; o; o >>= 1) {
            s  += __shfl_xor_sync(0xffffffffu, s,  o);
            ss += __shfl_xor_sync(0xffffffffu, ss, o);
        }
        float mu   = s * (1.0f / CZ);
        float var  = ss * (1.0f / CZ) - mu * mu;
        float rstd = rsqrtf(var + LN_EPS);

        const float4* zr = reinterpret_cast<const float4*>(z + (size_t)row * CZ);
        const float4* wv = reinterpret_cast<const float4*>(ln_z_w);
        const float4* tv = reinterpret_cast<const float4*>(&tab_g[bin * CZ]);
        float4* ov = reinterpret_cast<float4*>(out_z + (size_t)row * CZ);

        {
            float4 a = __ldcs(zr + h);
            float4 w = wv[h], t = tv[h];
            float4 o;
            o.x = a.x + t.x + (v0.x - mu) * rstd * w.x;
            o.y = a.y + t.y + (v0.y - mu) * rstd * w.y;
            o.z = a.z + t.z + (v0.z - mu) * rstd * w.z;
            o.w = a.w + t.w + (v0.w - mu) * rstd * w.w;
            __stcs(ov + h, o);
        }
        {
            float4 a = __ldcs(zr + h + 16);
            float4 w = wv[h + 16], t = tv[h + 16];
            float4 o;
            o.x = a.x + t.x + (v1.x - mu) * rstd * w.x;
            o.y = a.y + t.y + (v1.y - mu) * rstd * w.y;
            o.z = a.z + t.z + (v1.z - mu) * rstd * w.z;
            o.w = a.w + t.w + (v1.w - mu) * rstd * w.w;
            __stcs(ov + h + 16, o);
        }
    } else if (bid < NSETUP) {
        // ------------------------------------------------------------------
        // Table setup: block k computes tab_g[k][0..127]; fence before retire
        // so the stores are L2-visible when the (much later) z blocks read.
        // ------------------------------------------------------------------
        int k = bid;
        int c = threadIdx.x;
        if (c < CZ) {
            float v = lin_b[c] + ln_z_b[c];
            if (k < 15) v += lin_w[c * 15 + k];
            tab_g[k * CZ + c] = v;
        }
        __syncthreads();
        if (threadIdx.x == 0)
            __threadfence();                       // release tab_g writes
    } else if (bid < M_BASE) {
        // ------------------------------------------------------------------
        // bulk copy of m[1:,...] -> out : 4 float4/thread (lean: 32 regs)
        // ------------------------------------------------------------------
        unsigned cb = bid - COPY_BASE;
        const float4* src = reinterpret_cast<const float4*>(m);
        float4* dst = reinterpret_cast<float4*>(out);
        size_t base = (size_t)M_SKIP4 + (size_t)cb * 1024 + threadIdx.x;
        #pragma unroll
        for (int k = 0; k < 4; k++)
            __stcs(dst + base + k * 256, __ldcs(src + base + k * 256));
    } else {
        // ------------------------------------------------------------------
        // m slice 0: out[0,n,:] = m[0,n,:] + LN(m_prev[0,n,:])
        // 1 warp per row, 8 rows/block.
        // ------------------------------------------------------------------
        int mb   = bid - M_BASE;
        int wid  = threadIdx.x >> 5;
        int lane = threadIdx.x & 31;
        int row  = mb * 8 + wid;

        const float4* mp = reinterpret_cast<const float4*>(m_prev + (size_t)row * CM);
        float4 a = mp[lane];
        float4 b = mp[lane + 32];

        float s  = a.x + a.y + a.z + a.w + b.x + b.y + b.z + b.w;
        float ss = a.x*a.x + a.y*a.y + a.z*a.z + a.w*a.w
                 + b.x*b.x + b.y*b.y + b.z*b.z + b.w*b.w;
        #pragma unroll
        for (int o = 16; o; o >>= 1) {
            s  += __shfl_xor_sync(0xffffffffu, s,  o);
            ss += __shfl_xor_sync(0xffffffffu, ss, o);
        }
        float mu   = s * (1.0f / CM);
        float var  = ss * (1.0f / CM) - mu * mu;
        float rstd = rsqrtf(var + LN_EPS);

        const float4* mr = reinterpret_cast<const float4*>(m + (size_t)row * CM);
        const float4* wv = reinterpret_cast<const float4*>(ln_m_w);
        const float4* bv = reinterpret_cast<const float4*>(ln_m_b);
        float4* ov = reinterpret_cast<float4*>(out + (size_t)row * CM);

        {
            float4 mm = mr[lane], w = wv[lane], bb = bv[lane];
            float4 o;
            o.x = mm.x + (a.x - mu) * rstd * w.x + bb.x;
            o.y = mm.y + (a.y - mu) * rstd * w.y + bb.y;
            o.z = mm.z + (a.z - mu) * rstd * w.z + bb.z;
            o.w = mm.w + (a.w - mu) * rstd * w.w + bb.w;
            ov[lane] = o;
        }
        {
            float4 mm = mr[lane + 32], w = wv[lane + 32], bb = bv[lane + 32];
            float4 o;
            o.x = mm.x + (b.x - mu) * rstd * w.x + bb.x;
            o.y = mm.y + (b.y - mu) * rstd * w.y + bb.y;
            o.z = mm.z + (b.z - mu) * rstd * w.z + bb.z;
            o.w = mm.w + (b.w - mu) * rstd * w.w + bb.w;
            ov[lane + 32] = o;
        }
    }
}

extern "C" void kernel_launch(void* const* d_in, const int* in_sizes, int n_in,
                              void* d_out, int out_size) {
    const float* m      = (const float*)d_in[0];
    const float* z      = (const float*)d_in[1];
    const float* m_prev = (const float*)d_in[2];
    const float* z_prev = (const float*)d_in[3];
    const float* x_prev = (const float*)d_in[4];
    const float* ln_m_w = (const float*)d_in[5];
    const float* ln_m_b = (const float*)d_in[6];
    const float* ln_z_w = (const float*)d_in[7];
    const float* ln_z_b = (const float*)d_in[8];
    const float* lin_w  = (const float*)d_in[9];
    const float* lin_b  = (const float*)d_in[10];

    fused_kernel<<<GRID_TOTAL, 256>>>(
        m, z, m_prev, z_prev, x_prev,
        ln_m_w, ln_m_b, ln_z_w, ln_z_b, lin_w, lin_b, (float*)d_out);
}

// round 17
// speedup vs baseline: 1.0179x; 1.0054x over previous
#include <cuda_runtime.h>

#define CM 256
#define CZ 128
#define NRES 768
#define SDIM 128
#define LN_EPS 1e-5f

// Block-role layout (single fused kernel, 256 threads/block):
//   [0, 16)            : table setup (one bin per block)
//   [16, 16+6096)      : bulk m copy (skipping slice 0), 4 float4/thread
//   [6112, 6112+96)    : m row-0 LN-add, 8 rows/block
//   [6208, 6208+36864) : z path, 16 rows/block (2 rows/warp)
//
// Ordering argument (why the z path needs NO table guard): blocks are
// dispatched in bid order; a z block (bid >= 6208) can only be dispatched
// after 6208-1184 = 5024 earlier blocks have RETIRED (1184 = 148 SMs x 8
// resident blocks). The 6096 copy blocks between setup and z each move 16KB
// (>= 1us lifetime), i.e. >= 4 full block generations of wall time separate
// setup retirement from the first z dispatch. Setup blocks (bid 0-15, wave-1
// resident, ~300ns) end with __threadfence, so their tab_g stores are
// L2-visible long before any z block issues its first load. tab_g is never
// read before the z phase, so no SM can hold a stale L1 copy. This holds
// identically on every replay (deterministic dispatch).
#define NSETUP       16
#define NCOPY_BLOCKS 6096    // (25165824 - 196608)/4/1024
#define NM_BLOCKS    96      // 768 / 8
#define NZ_BLOCKS    36864   // 589824 / 16
#define COPY_BASE    NSETUP
#define M_BASE       (NSETUP + NCOPY_BLOCKS)
#define Z_BASE       (NSETUP + NCOPY_BLOCKS + NM_BLOCKS)
#define GRID_TOTAL   (NSETUP + NCOPY_BLOCKS + NM_BLOCKS + NZ_BLOCKS)
#define M_ELEMS      25165824
#define M_SKIP4      49152   // 768*256/4

// tab_g[k][c] = lin_w[c*15+k] + lin_b[c] + ln_z_b[c] (k<15); tab_g[15][c] = lin_b[c]+ln_z_b[c]
__device__ float tab_g[16 * CZ];

__global__ void __launch_bounds__(256, 8) fused_kernel(
        const float* __restrict__ m,
        const float* __restrict__ z,
        const float* __restrict__ m_prev,
        const float* __restrict__ z_prev,
        const float* __restrict__ x,
        const float* __restrict__ ln_m_w,
        const float* __restrict__ ln_m_b,
        const float* __restrict__ ln_z_w,
        const float* __restrict__ ln_z_b,
        const float* __restrict__ lin_w,
        const float* __restrict__ lin_b,
        float* __restrict__ out) {

    float* out_z = out + M_ELEMS;
    const unsigned bid = blockIdx.x;

    if (bid >= Z_BASE) {
        // ------------------------------------------------------------------
        // z path: out_z[row,:] = z[row,:] + LN(z_prev[row,:]) + tab[bin,:]
        // 2 rows per warp: half-warp per row, 8 floats per lane.
        // No guard needed — see ordering argument above.
        // ------------------------------------------------------------------
        int zb   = bid - Z_BASE;
        int wid  = threadIdx.x >> 5;
        int lane = threadIdx.x & 31;
        int h    = lane & 15;
        int row  = zb * 16 + wid * 2 + (lane >> 4);

        int i = row / NRES;
        int j = row - i * NRES;

        // Distance with UNFUSED fp32 arithmetic — matches the reference's
        // (dx*dx + dy*dy) + dz*dz rounding so edge-adjacent d values bin
        // identically.
        float dx = x[3 * i + 0] - x[3 * j + 0];
        float dy = x[3 * i + 1] - x[3 * j + 1];
        float dz = x[3 * i + 2] - x[3 * j + 2];
        float s2 = __fadd_rn(__fadd_rn(__fmul_rn(dx, dx), __fmul_rn(dy, dy)),
                             __fmul_rn(dz, dz));
        float d  = sqrtf(s2);

        // Robust bin: clamp k0 to 15 so d >> 20.75 still tests the open-ended
        // bin 14 (candidates {14,15,16}); +/-1 loop absorbs floor() rounding;
        // edges 3.25+1.25k are fp32-exact so the test matches the reference.
        int bin = 15;
        int k0 = (int)floorf((d - 3.25f) * 0.8f);
        if (k0 > 15) k0 = 15;
        #pragma unroll
        for (int dk = -1; dk <= 1; dk++) {
            int k = k0 + dk;
            if (k >= 0 && k <= 14) {
                float lo = fmaf(1.25f, (float)k, 3.25f);
                float hi = (k == 14) ? 1e8f : (lo + 1.25f);
                if (d > lo && d < hi) bin = k;
            }
        }

        const float4* zp = reinterpret_cast<const float4*>(z_prev + (size_t)row * CZ);
        float4 v0 = __ldcs(zp + h);
        float4 v1 = __ldcs(zp + h + 16);

        float s  = v0.x + v0.y + v0.z + v0.w + v1.x + v1.y + v1.z + v1.w;
        float ss = v0.x*v0.x + v0.y*v0.y + v0.z*v0.z + v0.w*v0.w
                 + v1.x*v1.x + v1.y*v1.y + v1.z*v1.z + v1.w*v1.w;
        #pragma unroll
        for (int o = 8; o; o >>= 1) {
            s  += __shfl_xor_sync(0xffffffffu, s,  o);
            ss += __shfl_xor_sync(0xffffffffu, ss, o);
        }
        float mu   = s * (1.0f / CZ);
        float var  = ss * (1.0f / CZ) - mu * mu;
        float rstd = rsqrtf(var + LN_EPS);

        const float4* zr = reinterpret_cast<const float4*>(z + (size_t)row * CZ);
        const float4* wv = reinterpret_cast<const float4*>(ln_z_w);
        const float4* tv = reinterpret_cast<const float4*>(&tab_g[bin * CZ]);
        float4* ov = reinterpret_cast<float4*>(out_z + (size_t)row * CZ);

        {
            float4 a = __ldcs(zr + h);
            float4 w = wv[h], t = tv[h];
            float4 o;
            o.x = a.x + t.x + (v0.x - mu) * rstd * w.x;
            o.y = a.y + t.y + (v0.y - mu) * rstd * w.y;
            o.z = a.z + t.z + (v0.z - mu) * rstd * w.z;
            o.w = a.w + t.w + (v0.w - mu) * rstd * w.w;
            __stcs(ov + h, o);
        }
        {
            float4 a = __ldcs(zr + h + 16);
            float4 w = wv[h + 16], t = tv[h + 16];
            float4 o;
            o.x = a.x + t.x + (v1.x - mu) * rstd * w.x;
            o.y = a.y + t.y + (v1.y - mu) * rstd * w.y;
            o.z = a.z + t.z + (v1.z - mu) * rstd * w.z;
            o.w = a.w + t.w + (v1.w - mu) * rstd * w.w;
            __stcs(ov + h + 16, o);
        }
    } else if (bid < NSETUP) {
        // ------------------------------------------------------------------
        // Table setup: block k computes tab_g[k][0..127]; fence before retire
        // so the stores are L2-visible when the (much later) z blocks read.
        // ------------------------------------------------------------------
        int k = bid;
        int c = threadIdx.x;
        if (c < CZ) {
            float v = lin_b[c] + ln_z_b[c];
            if (k < 15) v += lin_w[c * 15 + k];
            tab_g[k * CZ + c] = v;
        }
        __syncthreads();
        if (threadIdx.x == 0)
            __threadfence();                       // release tab_g writes
    } else if (bid < M_BASE) {
        // ------------------------------------------------------------------
        // bulk copy of m[1:,...] -> out : 4 float4/thread (lean: 32 regs)
        // ------------------------------------------------------------------
        unsigned cb = bid - COPY_BASE;
        const float4* src = reinterpret_cast<const float4*>(m);
        float4* dst = reinterpret_cast<float4*>(out);
        size_t base = (size_t)M_SKIP4 + (size_t)cb * 1024 + threadIdx.x;
        #pragma unroll
        for (int k = 0; k < 4; k++)
            __stcs(dst + base + k * 256, __ldcs(src + base + k * 256));
    } else {
        // ------------------------------------------------------------------
        // m slice 0: out[0,n,:] = m[0,n,:] + LN(m_prev[0,n,:])
        // 1 warp per row, 8 rows/block.
        // ------------------------------------------------------------------
        int mb   = bid - M_BASE;
        int wid  = threadIdx.x >> 5;
        int lane = threadIdx.x & 31;
        int row  = mb * 8 + wid;

        const float4* mp = reinterpret_cast<const float4*>(m_prev + (size_t)row * CM);
        float4 a = mp[lane];
        float4 b = mp[lane + 32];

        float s  = a.x + a.y + a.z + a.w + b.x + b.y + b.z + b.w;
        float ss = a.x*a.x + a.y*a.y + a.z*a.z + a.w*a.w
                 + b.x*b.x + b.y*b.y + b.z*b.z + b.w*b.w;
        #pragma unroll
        for (int o = 16; o; o >>= 1) {
            s  += __shfl_xor_sync(0xffffffffu, s,  o);
            ss += __shfl_xor_sync(0xffffffffu, ss, o);
        }
        float mu   = s * (1.0f / CM);
        float var  = ss * (1.0f / CM) - mu * mu;
        float rstd = rsqrtf(var + LN_EPS);

        const float4* mr = reinterpret_cast<const float4*>(m + (size_t)row * CM);
        const float4* wv = reinterpret_cast<const float4*>(ln_m_w);
        const float4* bv = reinterpret_cast<const float4*>(ln_m_b);
        float4* ov = reinterpret_cast<float4*>(out + (size_t)row * CM);

        {
            float4 mm = mr[lane], w = wv[lane], bb = bv[lane];
            float4 o;
            o.x = mm.x + (a.x - mu) * rstd * w.x + bb.x;
            o.y = mm.y + (a.y - mu) * rstd * w.y + bb.y;
            o.z = mm.z + (a.z - mu) * rstd * w.z + bb.z;
            o.w = mm.w + (a.w - mu) * rstd * w.w + bb.w;
            ov[lane] = o;
        }
        {
            float4 mm = mr[lane + 32], w = wv[lane + 32], bb = bv[lane + 32];
            float4 o;
            o.x = mm.x + (b.x - mu) * rstd * w.x + bb.x;
            o.y = mm.y + (b.y - mu) * rstd * w.y + bb.y;
            o.z = mm.z + (b.z - mu) * rstd * w.z + bb.z;
            o.w = mm.w + (b.w - mu) * rstd * w.w + bb.w;
            ov[lane + 32] = o;
        }
    }
}

extern "C" void kernel_launch(void* const* d_in, const int* in_sizes, int n_in,
                              void* d_out, int out_size) {
    const float* m      = (const float*)d_in[0];
    const float* z      = (const float*)d_in[1];
    const float* m_prev = (const float*)d_in[2];
    const float* z_prev = (const float*)d_in[3];
    const float* x_prev = (const float*)d_in[4];
    const float* ln_m_w = (const float*)d_in[5];
    const float* ln_m_b = (const float*)d_in[6];
    const float* ln_z_w = (const float*)d_in[7];
    const float* ln_z_b = (const float*)d_in[8];
    const float* lin_w  = (const float*)d_in[9];
    const float* lin_b  = (const float*)d_in[10];

    fused_kernel<<<GRID_TOTAL, 256>>>(
        m, z, m_prev, z_prev, x_prev,
        ln_m_w, ln_m_b, ln_z_w, ln_z_b, lin_w, lin_b, (float*)d_out);
}